// round 8
// baseline (speedup 1.0000x reference)
#include <cuda_runtime.h>
#include <cuda_bf16.h>
#include <math_constants.h>
#include <cstdint>

#define SEQ 1024
#define BSZ 8
#define EMBED 512
#define NH 8
#define QHD 32
#define PD 4
#define IN_PROJ 544

__device__ float g_Q[BSZ * NH * SEQ * QHD];   // 8 MB
__device__ float g_K[BSZ * NH * SEQ * QHD];   // 8 MB
__device__ float g_P[BSZ * NH * SEQ * PD];    // 1 MB

// ---------------------------------------------------------------------------
// Kernel 1: projection (round-1/4 version, ~150us).
// ---------------------------------------------------------------------------
__global__ __launch_bounds__(256) void proj_kernel(
    const float* __restrict__ x, const float* __restrict__ W,
    const float* __restrict__ bias)
{
    __shared__ float As[16][64];
    __shared__ float Bs[16][64];

    const int tid = threadIdx.x;
    const int m0 = blockIdx.y * 64;
    const int n0 = blockIdx.x * 64;
    const int tx = tid & 15;
    const int ty = tid >> 4;
    const int lr = tid >> 2;
    const int lc = (tid & 3) * 4;

    float acc[4][4];
#pragma unroll
    for (int i = 0; i < 4; i++)
#pragma unroll
        for (int j = 0; j < 4; j++) acc[i][j] = 0.f;

    for (int k0 = 0; k0 < EMBED; k0 += 16) {
        float4 av = *(const float4*)&x[(size_t)(m0 + lr) * EMBED + k0 + lc];
        float4 bv = make_float4(0.f, 0.f, 0.f, 0.f);
        if (n0 + lr < IN_PROJ)
            bv = *(const float4*)&W[(size_t)(n0 + lr) * EMBED + k0 + lc];
        As[lc + 0][lr] = av.x; As[lc + 1][lr] = av.y;
        As[lc + 2][lr] = av.z; As[lc + 3][lr] = av.w;
        Bs[lc + 0][lr] = bv.x; Bs[lc + 1][lr] = bv.y;
        Bs[lc + 2][lr] = bv.z; Bs[lc + 3][lr] = bv.w;
        __syncthreads();
#pragma unroll
        for (int k = 0; k < 16; k++) {
            float4 a = *(const float4*)&As[k][ty * 4];
            float4 b = *(const float4*)&Bs[k][tx * 4];
            float aa[4] = {a.x, a.y, a.z, a.w};
            float bb[4] = {b.x, b.y, b.z, b.w};
#pragma unroll
            for (int i = 0; i < 4; i++)
#pragma unroll
                for (int j = 0; j < 4; j++) acc[i][j] += aa[i] * bb[j];
        }
        __syncthreads();
    }

#pragma unroll
    for (int i = 0; i < 4; i++) {
        const int m = m0 + ty * 4 + i;
        const int s = m >> 3;
        const int bb = m & 7;
#pragma unroll
        for (int j = 0; j < 4; j++) {
            const int n = n0 + tx * 4 + j;
            if (n >= IN_PROJ) continue;
            const float v = acc[i][j] + bias[n];
            if (n < 256) {
                const int hh = n >> 5, d = n & 31;
                g_Q[(((size_t)(bb * NH + hh)) * SEQ + s) * QHD + d] = v;
            } else if (n < 512) {
                const int g = n - 256;
                const int hh = g >> 5, d = g & 31;
                g_K[(((size_t)(bb * NH + hh)) * SEQ + s) * QHD + d] = v;
            } else {
                const int g = n - 512;
                const int hh = g >> 2, d = g & 3;
                g_P[(((size_t)(bb * NH + hh)) * SEQ + s) * PD + d] = v;
            }
        }
    }
}

// ========================= warp-MMA plumbing (sm_80+) =======================
__device__ __forceinline__ uint32_t smem_u32(const void* p) {
    uint32_t a;
    asm("{ .reg .u64 t; cvta.to.shared.u64 t, %1; cvt.u32.u64 %0, t; }"
        : "=r"(a) : "l"(p));
    return a;
}

#define LDSM4(d0, d1, d2, d3, a) \
    asm volatile("ldmatrix.sync.aligned.m8n8.x4.shared.b16 {%0,%1,%2,%3}, [%4];" \
                 : "=r"(d0), "=r"(d1), "=r"(d2), "=r"(d3) : "r"(a))

__device__ __forceinline__ void mma16816(float* d, const uint32_t* a,
                                         uint32_t b0, uint32_t b1) {
    asm volatile(
        "mma.sync.aligned.m16n8k16.row.col.f32.bf16.bf16.f32 "
        "{%0,%1,%2,%3}, {%4,%5,%6,%7}, {%8,%9}, {%0,%1,%2,%3};"
        : "+f"(d[0]), "+f"(d[1]), "+f"(d[2]), "+f"(d[3])
        : "r"(a[0]), "r"(a[1]), "r"(a[2]), "r"(a[3]), "r"(b0), "r"(b1));
}

// convert 8 consecutive f32 into hi/lo bf16x2 quads: hi at row+c*16, lo at +64
__device__ __forceinline__ void cvt8p(const float* __restrict__ src,
                                      char* __restrict__ row, int c) {
    float4 v0 = *(const float4*)src;
    float4 v1 = *(const float4*)(src + 4);
    float f[8] = {v0.x, v0.y, v0.z, v0.w, v1.x, v1.y, v1.z, v1.w};
    uint32_t hp[4], lp[4];
#pragma unroll
    for (int p = 0; p < 4; p++) {
        float a = f[2 * p], bq = f[2 * p + 1];
        __nv_bfloat16 ah = __float2bfloat16(a);
        __nv_bfloat16 bh = __float2bfloat16(bq);
        __nv_bfloat162 hh; hh.x = ah; hh.y = bh;
        __nv_bfloat162 ll;
        ll.x = __float2bfloat16(a - __bfloat162float(ah));
        ll.y = __float2bfloat16(bq - __bfloat162float(bh));
        hp[p] = *(uint32_t*)&hh;
        lp[p] = *(uint32_t*)&ll;
    }
    *(uint4*)(row + c * 16) = make_uint4(hp[0], hp[1], hp[2], hp[3]);
    *(uint4*)(row + 64 + c * 16) = make_uint4(lp[0], lp[1], lp[2], lp[3]);
}

// ---------------------------------------------------------------------------
// Kernel 2: QK^T on HMMA (bf16 hi/lo split, 6 mma per 16x8 tile).
// CTA = (b, h, 16 t-rows, full s=1024). 8 warps, warp w owns s in [128w,128w+128).
// K chunked: 256 rows (hi|lo in 144B-pitch rows) per stage, 4 chunks.
// B fragments via NON-trans ldmatrix: SMEM rows are s(=n), cols are k, which is
// exactly the mma .col B fragment layout (pairs of consecutive k at fixed n).
// ---------------------------------------------------------------------------
#define KPITCH 144
#define SCK 256   // K rows per chunk

__global__ __launch_bounds__(256, 2)
void attn_mma_kernel(const float* __restrict__ pos, const float* __restrict__ off,
                     float* __restrict__ out)
{
    __shared__ __align__(16) char Ksm[SCK * KPITCH];   // 36864 B
    __shared__ __align__(16) char Qsm[16 * KPITCH];    // 2304 B
    __shared__ float4 Ps[16];
    __shared__ float red[16 * 8];
    __shared__ float invs[16];

    const int tid = threadIdx.x;
    const int w = tid >> 5, lane = tid & 31;
    const int t0g = blockIdx.x * 16;
    const int h = blockIdx.y, b = blockIdx.z;

    const float* Qg = g_Q + ((size_t)(b * NH + h)) * SEQ * QHD + (size_t)t0g * QHD;
    const float* Kg = g_K + ((size_t)(b * NH + h)) * SEQ * QHD;
    const float* Pg = g_P + ((size_t)(b * NH + h)) * SEQ * PD;

    // stage Q (16 rows x 4 k-octs) + P
    if (tid < 64) {
        const int r = tid >> 2, c = tid & 3;
        cvt8p(&Qg[(size_t)r * QHD + c * 8], Qsm + r * KPITCH, c);
    }
    if (tid < 16)
        Ps[tid] = *(const float4*)&Pg[(size_t)(t0g + tid) * PD];
    __syncthreads();

    const uint32_t Qaddr = smem_u32(Qsm);
    const uint32_t Kaddr = smem_u32(Ksm);

    // A fragments (persistent): [prec][kstep][4]
    // lanes 0-7: rows 0-7 @k0; 8-15: rows 8-15 @k0; 16-23: rows 0-7 @k+8;
    // 24-31: rows 8-15 @k+8  -> regs {(r,k),(r+8,k),(r,k+8),(r+8,k+8)}
    uint32_t aq[2][2][4];
    {
        const int arow = (lane & 7) + ((lane >> 3) & 1) * 8;
        const int ab = ((lane >> 4) & 1) * 16;
#pragma unroll
        for (int prec = 0; prec < 2; prec++)
#pragma unroll
            for (int kk = 0; kk < 2; kk++) {
                const uint32_t ad = Qaddr + arow * KPITCH + ab + kk * 32 + prec * 64;
                LDSM4(aq[prec][kk][0], aq[prec][kk][1],
                      aq[prec][kk][2], aq[prec][kk][3], ad);
            }
    }
    // per-lane P vectors (t rows l>>2 and +8)
    const int r0 = lane >> 2, r1 = r0 + 8;
    const float4 p0 = Ps[r0], p1 = Ps[r1];
    const int scol = 2 * (lane & 3);

    float sc_[4][4][4];   // [chunk][tile][v00,v01,v10,v11]
    float sum0 = 0.f, sum1 = 0.f;

    const int t0r = t0g + r0, t1r = t0g + r1;
    const float* pos0 = pos + (size_t)t0r * SEQ * PD;
    const float* pos1 = pos + (size_t)t1r * SEQ * PD;
    const float* off0 = off + ((size_t)b * SEQ + t0r) * SEQ;
    const float* off1 = off + ((size_t)b * SEQ + t1r) * SEQ;

#pragma unroll
    for (int ch = 0; ch < 4; ch++) {
        __syncthreads();   // previous chunk consumed
        // stage K chunk: 256 rows x 4 k-octs = 1024 slots over 256 threads
#pragma unroll
        for (int i = 0; i < 4; i++) {
            const int idx = tid + i * 256;
            const int r = idx >> 2, c = idx & 3;
            cvt8p(&Kg[(size_t)(ch * SCK + r) * QHD + c * 8], Ksm + r * KPITCH, c);
        }
        __syncthreads();

#pragma unroll
        for (int j = 0; j < 4; j++) {
            const int s0loc = w * 32 + j * 8;
            // B fragments via NON-trans ldmatrix.x4:
            // matrix m = rows s0loc..+7, k-bytes m*16 -> regs: k0-7,k8-15,k16-23,k24-31
            uint32_t bh[4], bl[4];
            {
                const uint32_t bad = Kaddr + (s0loc + (lane & 7)) * KPITCH +
                                     (lane >> 3) * 16;
                LDSM4(bh[0], bh[1], bh[2], bh[3], bad);
                LDSM4(bl[0], bl[1], bl[2], bl[3], bad + 64);
            }
            float ac[4] = {0.f, 0.f, 0.f, 0.f};
            mma16816(ac, aq[0][0], bh[0], bh[1]);   // qh*kh k0-15
            mma16816(ac, aq[0][1], bh[2], bh[3]);   // qh*kh k16-31
            mma16816(ac, aq[0][0], bl[0], bl[1]);   // qh*kl
            mma16816(ac, aq[0][1], bl[2], bl[3]);
            mma16816(ac, aq[1][0], bh[0], bh[1]);   // ql*kh
            mma16816(ac, aq[1][1], bh[2], bh[3]);

            // epilogue: + pos + off, exp, accumulate sums
            const int s = ch * SCK + s0loc + scol;
            const float4 pe0a = *(const float4*)&pos0[(size_t)s * PD];
            const float4 pe0b = *(const float4*)&pos0[(size_t)(s + 1) * PD];
            const float4 pe1a = *(const float4*)&pos1[(size_t)s * PD];
            const float4 pe1b = *(const float4*)&pos1[(size_t)(s + 1) * PD];
            const float2 o0 = *(const float2*)&off0[s];
            const float2 o1 = *(const float2*)&off1[s];

            float v00 = ac[0] + p0.x * pe0a.x + p0.y * pe0a.y +
                        p0.z * pe0a.z + p0.w * pe0a.w + o0.x;
            float v01 = ac[1] + p0.x * pe0b.x + p0.y * pe0b.y +
                        p0.z * pe0b.z + p0.w * pe0b.w + o0.y;
            float v10 = ac[2] + p1.x * pe1a.x + p1.y * pe1a.y +
                        p1.z * pe1a.z + p1.w * pe1a.w + o1.x;
            float v11 = ac[3] + p1.x * pe1b.x + p1.y * pe1b.y +
                        p1.z * pe1b.z + p1.w * pe1b.w + o1.y;
            v00 = __expf(v00); v01 = __expf(v01);
            v10 = __expf(v10); v11 = __expf(v11);
            sc_[ch][j][0] = v00; sc_[ch][j][1] = v01;
            sc_[ch][j][2] = v10; sc_[ch][j][3] = v11;
            sum0 += v00 + v01;
            sum1 += v10 + v11;
        }
    }

    // row sums: reduce over quad lanes (same row, different s-cols)
#pragma unroll
    for (int o_ = 1; o_ <= 2; o_ <<= 1) {
        sum0 += __shfl_xor_sync(0xffffffffu, sum0, o_);
        sum1 += __shfl_xor_sync(0xffffffffu, sum1, o_);
    }
    if ((lane & 3) == 0) {
        red[r0 * 8 + w] = sum0;
        red[r1 * 8 + w] = sum1;
    }
    __syncthreads();
    if (tid < 16) {
        float s_ = 0.f;
#pragma unroll
        for (int ww = 0; ww < 8; ww++) s_ += red[tid * 8 + ww];
        invs[tid] = 1.0f / s_;
    }
    __syncthreads();

    const float inv0 = invs[r0], inv1 = invs[r1];
    float* out0 = out + (((size_t)(h * BSZ + b)) * SEQ + t0r) * SEQ;
    float* out1 = out + (((size_t)(h * BSZ + b)) * SEQ + t1r) * SEQ;

#pragma unroll
    for (int ch = 0; ch < 4; ch++)
#pragma unroll
        for (int j = 0; j < 4; j++) {
            const int s = ch * SCK + w * 32 + j * 8 + scol;
            *(float2*)&out0[s] = make_float2(sc_[ch][j][0] * inv0,
                                             sc_[ch][j][1] * inv0);
            *(float2*)&out1[s] = make_float2(sc_[ch][j][2] * inv1,
                                             sc_[ch][j][3] * inv1);
        }
}

// ---------------------------------------------------------------------------
extern "C" void kernel_launch(void* const* d_in, const int* in_sizes, int n_in,
                              void* d_out, int out_size)
{
    const float* x    = (const float*)d_in[0];
    const float* pos  = (const float*)d_in[1];
    const float* off  = (const float*)d_in[2];
    const float* W    = (const float*)d_in[3];
    const float* bias = (const float*)d_in[4];
    float* out = (float*)d_out;

    dim3 gproj((IN_PROJ + 63) / 64, (SEQ * BSZ) / 64);   // 9 x 128
    proj_kernel<<<gproj, 256>>>(x, W, bias);

    dim3 gattn(SEQ / 16, NH, BSZ);                        // 64 x 8 x 8
    attn_mma_kernel<<<gattn, 256>>>(pos, off, out);
}

// round 9
// speedup vs baseline: 1.0964x; 1.0964x over previous
#include <cuda_runtime.h>
#include <cuda_bf16.h>
#include <cstdint>

#define SEQ 1024
#define BSZ 8
#define EMBED 512
#define NH 8
#define QHD 32
#define PD 4
#define IN_PROJ 544

// Q/K stored as packed hi/lo bf16 rows: 128B per (s) row = [hi bf16 x32 | lo bf16 x32]
__device__ __align__(16) char g_Qhl[BSZ * NH * SEQ * 128];   // 8 MB
__device__ __align__(16) char g_Khl[BSZ * NH * SEQ * 128];   // 8 MB
__device__ float g_P[BSZ * NH * SEQ * PD];                   // 1 MB

// ---------------------------------------------------------------------------
// Kernel 1: projection; writes Q/K as hi/lo bf16 packed rows, P as f32.
// ---------------------------------------------------------------------------
__global__ __launch_bounds__(256) void proj_kernel(
    const float* __restrict__ x, const float* __restrict__ W,
    const float* __restrict__ bias)
{
    __shared__ float As[16][64];
    __shared__ float Bs[16][64];

    const int tid = threadIdx.x;
    const int m0 = blockIdx.y * 64;
    const int n0 = blockIdx.x * 64;
    const int tx = tid & 15;
    const int ty = tid >> 4;
    const int lr = tid >> 2;
    const int lc = (tid & 3) * 4;

    float acc[4][4];
#pragma unroll
    for (int i = 0; i < 4; i++)
#pragma unroll
        for (int j = 0; j < 4; j++) acc[i][j] = 0.f;

    for (int k0 = 0; k0 < EMBED; k0 += 16) {
        float4 av = *(const float4*)&x[(size_t)(m0 + lr) * EMBED + k0 + lc];
        float4 bv = make_float4(0.f, 0.f, 0.f, 0.f);
        if (n0 + lr < IN_PROJ)
            bv = *(const float4*)&W[(size_t)(n0 + lr) * EMBED + k0 + lc];
        As[lc + 0][lr] = av.x; As[lc + 1][lr] = av.y;
        As[lc + 2][lr] = av.z; As[lc + 3][lr] = av.w;
        Bs[lc + 0][lr] = bv.x; Bs[lc + 1][lr] = bv.y;
        Bs[lc + 2][lr] = bv.z; Bs[lc + 3][lr] = bv.w;
        __syncthreads();
#pragma unroll
        for (int k = 0; k < 16; k++) {
            float4 a = *(const float4*)&As[k][ty * 4];
            float4 b = *(const float4*)&Bs[k][tx * 4];
            float aa[4] = {a.x, a.y, a.z, a.w};
            float bb[4] = {b.x, b.y, b.z, b.w};
#pragma unroll
            for (int i = 0; i < 4; i++)
#pragma unroll
                for (int j = 0; j < 4; j++) acc[i][j] += aa[i] * bb[j];
        }
        __syncthreads();
    }

#pragma unroll
    for (int i = 0; i < 4; i++) {
        const int m = m0 + ty * 4 + i;
        const int s = m >> 3;
        const int bb = m & 7;
#pragma unroll
        for (int j = 0; j < 4; j++) {
            const int n = n0 + tx * 4 + j;
            if (n >= IN_PROJ) continue;
            const float v = acc[i][j] + bias[n];
            if (n < 512) {
                const int qk = (n >= 256);
                const int g = n - qk * 256;
                const int hh = g >> 5, d = g & 31;
                char* row = (qk ? g_Khl : g_Qhl) +
                            (((size_t)(bb * NH + hh)) * SEQ + s) * 128;
                __nv_bfloat16 hi = __float2bfloat16(v);
                __nv_bfloat16 lo = __float2bfloat16(v - __bfloat162float(hi));
                *(__nv_bfloat16*)(row + d * 2) = hi;
                *(__nv_bfloat16*)(row + 64 + d * 2) = lo;
            } else {
                const int g = n - 512;
                const int hh = g >> 2, d = g & 3;
                g_P[(((size_t)(bb * NH + hh)) * SEQ + s) * PD + d] = v;
            }
        }
    }
}

// ========================= warp-MMA plumbing (sm_80+) =======================
__device__ __forceinline__ uint32_t smem_u32(const void* p) {
    uint32_t a;
    asm("{ .reg .u64 t; cvta.to.shared.u64 t, %1; cvt.u32.u64 %0, t; }"
        : "=r"(a) : "l"(p));
    return a;
}

#define LDSM4(d0, d1, d2, d3, a) \
    asm volatile("ldmatrix.sync.aligned.m8n8.x4.shared.b16 {%0,%1,%2,%3}, [%4];" \
                 : "=r"(d0), "=r"(d1), "=r"(d2), "=r"(d3) : "r"(a))

__device__ __forceinline__ void mma16816(float* d, const uint32_t* a,
                                         uint32_t b0, uint32_t b1) {
    asm volatile(
        "mma.sync.aligned.m16n8k16.row.col.f32.bf16.bf16.f32 "
        "{%0,%1,%2,%3}, {%4,%5,%6,%7}, {%8,%9}, {%0,%1,%2,%3};"
        : "+f"(d[0]), "+f"(d[1]), "+f"(d[2]), "+f"(d[3])
        : "r"(a[0]), "r"(a[1]), "r"(a[2]), "r"(a[3]), "r"(b0), "r"(b1));
}

// ---------------------------------------------------------------------------
// Kernel 2: QK^T on HMMA (hi/lo split), raw scores -> SMEM tile, then a fully
// coalesced epilogue (warp = t-row, lanes = contiguous s) with softmax.
// CTA = (b, h, 16 t-rows, full s=1024). 8 warps.
// ---------------------------------------------------------------------------
#define KPITCH 144
#define SCK 256            // K rows per chunk
#define SCP 1032           // score tile pitch in f32 words (8-bank row stagger)

#define SC_OFF  0                          // 16*1032*4 = 66048 B
#define K_OFF   66048                      // 256*144 = 36864 B
#define Q_OFF   (66048 + 36864)            // 16*144 = 2304 B
#define PS_OFF  (Q_OFF + 2304)             // 16*16 = 256 B
#define SM_TOTAL (PS_OFF + 256)            // 105472 B

__global__ __launch_bounds__(256, 2)
void attn_mma_kernel(const float* __restrict__ pos, const float* __restrict__ off,
                     float* __restrict__ out)
{
    extern __shared__ __align__(16) char smraw[];
    float* sc = (float*)(smraw + SC_OFF);
    char* Ksm = smraw + K_OFF;
    char* Qsm = smraw + Q_OFF;
    float4* Ps = (float4*)(smraw + PS_OFF);

    const int tid = threadIdx.x;
    const int w = tid >> 5, lane = tid & 31;
    const int t0g = blockIdx.x * 16;
    const int h = blockIdx.y, b = blockIdx.z;

    const char* Qg = g_Qhl + (((size_t)(b * NH + h)) * SEQ + t0g) * 128;
    const char* Kg = g_Khl + ((size_t)(b * NH + h)) * SEQ * 128;
    const float* Pg = g_P + ((size_t)(b * NH + h)) * SEQ * PD;

    // stage Q rows (16 x 128B) + P
    if (tid < 128) {
        const int r = tid >> 3, oct = tid & 7;
        *(uint4*)(Qsm + r * KPITCH + oct * 16) =
            *(const uint4*)(Qg + (size_t)r * 128 + oct * 16);
    }
    if (tid < 16)
        Ps[tid] = *(const float4*)&Pg[(size_t)(t0g + tid) * PD];
    __syncthreads();

    const uint32_t Qaddr = smem_u32(Qsm);
    const uint32_t Kaddr = smem_u32(Ksm);

    // A fragments (persistent): [prec][kstep][4]
    uint32_t aq[2][2][4];
    {
        const int arow = (lane & 7) + ((lane >> 3) & 1) * 8;
        const int ab = ((lane >> 4) & 1) * 16;
#pragma unroll
        for (int prec = 0; prec < 2; prec++)
#pragma unroll
            for (int kk = 0; kk < 2; kk++) {
                const uint32_t ad = Qaddr + arow * KPITCH + ab + kk * 32 + prec * 64;
                LDSM4(aq[prec][kk][0], aq[prec][kk][1],
                      aq[prec][kk][2], aq[prec][kk][3], ad);
            }
    }

    const int r0 = lane >> 2, r1 = r0 + 8;   // accumulator rows (t-local)
    const int scol = 2 * (lane & 3);

    // ---- phase 1: MMA -> raw scores in SMEM tile ---------------------------
#pragma unroll
    for (int ch = 0; ch < 4; ch++) {
        __syncthreads();   // previous chunk's B-frags consumed
        // stage K chunk: 256 rows x 8 uint4 = 2048 slots over 256 threads
#pragma unroll
        for (int i = 0; i < 8; i++) {
            const int idx = tid + i * 256;
            const int r = idx >> 3, oct = idx & 7;
            *(uint4*)(Ksm + r * KPITCH + oct * 16) =
                *(const uint4*)(Kg + (size_t)(ch * SCK + r) * 128 + oct * 16);
        }
        __syncthreads();

#pragma unroll
        for (int j = 0; j < 4; j++) {
            const int s0loc = w * 32 + j * 8;
            uint32_t bh[4], bl[4];
            {
                const uint32_t bad = Kaddr + (s0loc + (lane & 7)) * KPITCH +
                                     (lane >> 3) * 16;
                LDSM4(bh[0], bh[1], bh[2], bh[3], bad);
                LDSM4(bl[0], bl[1], bl[2], bl[3], bad + 64);
            }
            float ac[4] = {0.f, 0.f, 0.f, 0.f};
            mma16816(ac, aq[0][0], bh[0], bh[1]);   // qh*kh k0-15
            mma16816(ac, aq[0][1], bh[2], bh[3]);   // qh*kh k16-31
            mma16816(ac, aq[0][0], bl[0], bl[1]);   // qh*kl
            mma16816(ac, aq[0][1], bl[2], bl[3]);
            mma16816(ac, aq[1][0], bh[0], bh[1]);   // ql*kh
            mma16816(ac, aq[1][1], bh[2], bh[3]);

            const int col = ch * SCK + s0loc + scol;
            *(float2*)&sc[r0 * SCP + col] = make_float2(ac[0], ac[1]);
            *(float2*)&sc[r1 * SCP + col] = make_float2(ac[2], ac[3]);
        }
    }
    __syncthreads();

    // ---- phase 2: coalesced epilogue + softmax (warp = t-row) --------------
#pragma unroll
    for (int rr = 0; rr < 2; rr++) {
        const int tl = w * 2 + rr;
        const int t = t0g + tl;
        const float4 p4 = Ps[tl];
        const float* posrow = pos + (size_t)t * SEQ * PD;
        const float* offrow = off + ((size_t)b * SEQ + t) * SEQ;
        float* scrow = &sc[tl * SCP];

        float sum = 0.f;
#pragma unroll
        for (int i = 0; i < 32; i++) {
            const int s = i * 32 + lane;
            float v = scrow[s];
            const float4 pe = *(const float4*)&posrow[(size_t)s * PD];
            const float o = offrow[s];
            v += p4.x * pe.x + p4.y * pe.y + p4.z * pe.z + p4.w * pe.w + o;
            v = __expf(v);
            scrow[s] = v;
            sum += v;
        }
#pragma unroll
        for (int o_ = 16; o_ > 0; o_ >>= 1)
            sum += __shfl_xor_sync(0xffffffffu, sum, o_);
        const float inv = 1.0f / sum;

        float* orow = &out[(((size_t)(h * BSZ + b)) * SEQ + t) * SEQ];
#pragma unroll
        for (int i = 0; i < 8; i++) {
            float4 v = *(const float4*)&scrow[i * 128 + lane * 4];
            v.x *= inv; v.y *= inv; v.z *= inv; v.w *= inv;
            *(float4*)&orow[i * 128 + lane * 4] = v;
        }
    }
}

// ---------------------------------------------------------------------------
extern "C" void kernel_launch(void* const* d_in, const int* in_sizes, int n_in,
                              void* d_out, int out_size)
{
    const float* x    = (const float*)d_in[0];
    const float* pos  = (const float*)d_in[1];
    const float* off  = (const float*)d_in[2];
    const float* W    = (const float*)d_in[3];
    const float* bias = (const float*)d_in[4];
    float* out = (float*)d_out;

    cudaFuncSetAttribute(attn_mma_kernel,
                         cudaFuncAttributeMaxDynamicSharedMemorySize, SM_TOTAL);

    dim3 gproj((IN_PROJ + 63) / 64, (SEQ * BSZ) / 64);   // 9 x 128
    proj_kernel<<<gproj, 256>>>(x, W, bias);

    dim3 gattn(SEQ / 16, NH, BSZ);                        // 64 x 8 x 8
    attn_mma_kernel<<<gattn, 256, SM_TOTAL>>>(pos, off, out);
}

// round 10
// speedup vs baseline: 1.5595x; 1.4224x over previous
#include <cuda_runtime.h>
#include <cuda_bf16.h>
#include <cstdint>

#define SEQ 1024
#define BSZ 8
#define EMBED 512
#define NH 8
#define QHD 32
#define PD 4
#define IN_PROJ 544

// Q/K stored as packed hi/lo bf16 rows: 128B per (s) row = [hi bf16 x32 | lo bf16 x32]
__device__ __align__(16) char g_Qhl[BSZ * NH * SEQ * 128];   // 8 MB
__device__ __align__(16) char g_Khl[BSZ * NH * SEQ * 128];   // 8 MB
__device__ float g_P[BSZ * NH * SEQ * PD];                   // 1 MB

// ========================= warp-MMA plumbing (sm_80+) =======================
__device__ __forceinline__ uint32_t smem_u32(const void* p) {
    uint32_t a;
    asm("{ .reg .u64 t; cvta.to.shared.u64 t, %1; cvt.u32.u64 %0, t; }"
        : "=r"(a) : "l"(p));
    return a;
}

#define LDSM4(d0, d1, d2, d3, a) \
    asm volatile("ldmatrix.sync.aligned.m8n8.x4.shared.b16 {%0,%1,%2,%3}, [%4];" \
                 : "=r"(d0), "=r"(d1), "=r"(d2), "=r"(d3) : "r"(a))

__device__ __forceinline__ void mma16816(float* d, const uint32_t* a,
                                         uint32_t b0, uint32_t b1) {
    asm volatile(
        "mma.sync.aligned.m16n8k16.row.col.f32.bf16.bf16.f32 "
        "{%0,%1,%2,%3}, {%4,%5,%6,%7}, {%8,%9}, {%0,%1,%2,%3};"
        : "+f"(d[0]), "+f"(d[1]), "+f"(d[2]), "+f"(d[3])
        : "r"(a[0]), "r"(a[1]), "r"(a[2]), "r"(a[3]), "r"(b0), "r"(b1));
}

// split 8 consecutive f32 into hi/lo bf16x2 quads written to two SMEM planes
__device__ __forceinline__ void cvt8s(const float* __restrict__ src,
                                      char* __restrict__ hirow,
                                      char* __restrict__ lorow, int c,
                                      bool valid) {
    float f[8];
    if (valid) {
        float4 v0 = *(const float4*)src;
        float4 v1 = *(const float4*)(src + 4);
        f[0] = v0.x; f[1] = v0.y; f[2] = v0.z; f[3] = v0.w;
        f[4] = v1.x; f[5] = v1.y; f[6] = v1.z; f[7] = v1.w;
    } else {
#pragma unroll
        for (int i = 0; i < 8; i++) f[i] = 0.f;
    }
    uint32_t hp[4], lp[4];
#pragma unroll
    for (int p = 0; p < 4; p++) {
        float a = f[2 * p], bq = f[2 * p + 1];
        __nv_bfloat16 ah = __float2bfloat16(a);
        __nv_bfloat16 bh = __float2bfloat16(bq);
        __nv_bfloat162 hh; hh.x = ah; hh.y = bh;
        __nv_bfloat162 ll;
        ll.x = __float2bfloat16(a - __bfloat162float(ah));
        ll.y = __float2bfloat16(bq - __bfloat162float(bh));
        hp[p] = *(uint32_t*)&hh;
        lp[p] = *(uint32_t*)&ll;
    }
    *(uint4*)(hirow + c * 16) = make_uint4(hp[0], hp[1], hp[2], hp[3]);
    *(uint4*)(lorow + c * 16) = make_uint4(lp[0], lp[1], lp[2], lp[3]);
}

// ---------------------------------------------------------------------------
// Kernel 1: projection on HMMA. CTA = 128M x 64N, BK=64 chunks, hi/lo split.
// Epilogue: acc -> SMEM f32 tile -> packed hi/lo bf16 rows (g_Qhl/g_Khl) or
// f32 g_P, bias folded into accumulator init.
// ---------------------------------------------------------------------------
#define PPITCH 144
#define XHI_OFF 0                         // 128*144 = 18432
#define XLO_OFF 18432
#define WHI_OFF 36864                     // 64*144 = 9216
#define WLO_OFF 46080
#define PROJ_SMEM 55296
#define OTP 68                            // out tile pitch (f32 words)

__global__ __launch_bounds__(256, 2) void proj_mma_kernel(
    const float* __restrict__ x, const float* __restrict__ W,
    const float* __restrict__ bias)
{
    extern __shared__ __align__(16) char sm[];
    char* Xhi = sm + XHI_OFF;
    char* Xlo = sm + XLO_OFF;
    char* Whi = sm + WHI_OFF;
    char* Wlo = sm + WLO_OFF;
    float* OT = (float*)sm;               // reused after MMA

    const int tid = threadIdx.x;
    const int w = tid >> 5, lane = tid & 31;
    const int n0 = blockIdx.x * 64;
    const int m0 = blockIdx.y * 128;
    const int wm = w & 3;                 // 4 m-groups of 32
    const int wn = w >> 2;                // 2 n-groups of 32

    const uint32_t XhiA = smem_u32(Xhi), XloA = smem_u32(Xlo);
    const uint32_t WhiA = smem_u32(Whi), WloA = smem_u32(Wlo);

    const int r0 = lane >> 2;
    const int scol = 2 * (lane & 3);

    // acc[mt][nt][4], bias-initialized
    float acc[2][4][4];
#pragma unroll
    for (int mt = 0; mt < 2; mt++)
#pragma unroll
        for (int nt = 0; nt < 4; nt++) {
            const int c = n0 + wn * 32 + nt * 8 + scol;
            const float b0v = (c < IN_PROJ) ? bias[c] : 0.f;
            const float b1v = (c + 1 < IN_PROJ) ? bias[c + 1] : 0.f;
            acc[mt][nt][0] = b0v; acc[mt][nt][1] = b1v;
            acc[mt][nt][2] = b0v; acc[mt][nt][3] = b1v;
        }

    for (int k0 = 0; k0 < EMBED; k0 += 64) {
        __syncthreads();   // planes consumed by previous chunk
        // stage x chunk: 128 rows x 8 octs = 1024 slots
#pragma unroll
        for (int i = 0; i < 4; i++) {
            const int idx = tid + i * 256;
            const int r = idx >> 3, oct = idx & 7;
            cvt8s(&x[(size_t)(m0 + r) * EMBED + k0 + oct * 8],
                  Xhi + r * PPITCH, Xlo + r * PPITCH, oct, true);
        }
        // stage W chunk: 64 rows x 8 octs = 512 slots (guard n)
#pragma unroll
        for (int i = 0; i < 2; i++) {
            const int idx = tid + i * 256;
            const int r = idx >> 3, oct = idx & 7;
            cvt8s(&W[(size_t)(n0 + r) * EMBED + k0 + oct * 8],
                  Whi + r * PPITCH, Wlo + r * PPITCH, oct, n0 + r < IN_PROJ);
        }
        __syncthreads();

        const int arow = (lane & 7) + ((lane >> 3) & 1) * 8;
        const int ab = ((lane >> 4) & 1) * 16;
        const int brow = lane & 7, bb = (lane >> 3) * 16;

#pragma unroll
        for (int kh = 0; kh < 2; kh++) {
            // A frags: [mt][prec][kr][4]  (LDSM4 = m16 x k16 per (kr))
            uint32_t A[2][2][2][4];
#pragma unroll
            for (int mt = 0; mt < 2; mt++)
#pragma unroll
                for (int kr = 0; kr < 2; kr++) {
                    const uint32_t off =
                        (wm * 32 + mt * 16 + arow) * PPITCH + ab +
                        kh * 64 + kr * 32;
                    LDSM4(A[mt][0][kr][0], A[mt][0][kr][1],
                          A[mt][0][kr][2], A[mt][0][kr][3], XhiA + off);
                    LDSM4(A[mt][1][kr][0], A[mt][1][kr][1],
                          A[mt][1][kr][2], A[mt][1][kr][3], XloA + off);
                }
            // B frags: [nt][prec][4] (4 regs = k32 for one n8 block)
            uint32_t B[4][2][4];
#pragma unroll
            for (int nt = 0; nt < 4; nt++) {
                const uint32_t off =
                    (wn * 32 + nt * 8 + brow) * PPITCH + bb + kh * 64;
                LDSM4(B[nt][0][0], B[nt][0][1], B[nt][0][2], B[nt][0][3],
                      WhiA + off);
                LDSM4(B[nt][1][0], B[nt][1][1], B[nt][1][2], B[nt][1][3],
                      WloA + off);
            }
#pragma unroll
            for (int kr = 0; kr < 2; kr++)
#pragma unroll
                for (int mt = 0; mt < 2; mt++)
#pragma unroll
                    for (int nt = 0; nt < 4; nt++) {
                        mma16816(acc[mt][nt], A[mt][0][kr],
                                 B[nt][0][kr * 2], B[nt][0][kr * 2 + 1]);
                        mma16816(acc[mt][nt], A[mt][0][kr],
                                 B[nt][1][kr * 2], B[nt][1][kr * 2 + 1]);
                        mma16816(acc[mt][nt], A[mt][1][kr],
                                 B[nt][0][kr * 2], B[nt][0][kr * 2 + 1]);
                    }
        }
    }
    __syncthreads();   // done with planes; reuse as OT

    // acc -> SMEM f32 tile (128 x 64, pitch OTP)
#pragma unroll
    for (int mt = 0; mt < 2; mt++)
#pragma unroll
        for (int nt = 0; nt < 4; nt++) {
            const int mr0 = wm * 32 + mt * 16 + r0;
            const int c = wn * 32 + nt * 8 + scol;
            *(float2*)&OT[mr0 * OTP + c] =
                make_float2(acc[mt][nt][0], acc[mt][nt][1]);
            *(float2*)&OT[(mr0 + 8) * OTP + c] =
                make_float2(acc[mt][nt][2], acc[mt][nt][3]);
        }
    __syncthreads();

    // output pass: thread = (m row, 32-col half)
    const int mr = tid >> 1, half = tid & 1;
    const int m = m0 + mr;
    const int s = m >> 3, bb2 = m & 7;
    const int nb = blockIdx.x;
    const float* src = &OT[mr * OTP + half * 32];

    if (nb < 8) {
        // Q blocks nb 0-3, K blocks nb 4-7; h = (nb&3)*2 + half, d = 0..31
        const int qk = nb >> 2;
        const int hh = (nb & 3) * 2 + half;
        char* row = (qk ? g_Khl : g_Qhl) +
                    (((size_t)(bb2 * NH + hh)) * SEQ + s) * 128;
        uint32_t hp[16], lp[16];
#pragma unroll
        for (int p = 0; p < 16; p++) {
            const float a = src[2 * p], bq = src[2 * p + 1];
            __nv_bfloat16 ah = __float2bfloat16(a);
            __nv_bfloat16 bh = __float2bfloat16(bq);
            __nv_bfloat162 hh2; hh2.x = ah; hh2.y = bh;
            __nv_bfloat162 ll;
            ll.x = __float2bfloat16(a - __bfloat162float(ah));
            ll.y = __float2bfloat16(bq - __bfloat162float(bh));
            hp[p] = *(uint32_t*)&hh2;
            lp[p] = *(uint32_t*)&ll;
        }
#pragma unroll
        for (int q = 0; q < 4; q++) {
            *(uint4*)(row + q * 16) =
                make_uint4(hp[4 * q], hp[4 * q + 1], hp[4 * q + 2], hp[4 * q + 3]);
            *(uint4*)(row + 64 + q * 16) =
                make_uint4(lp[4 * q], lp[4 * q + 1], lp[4 * q + 2], lp[4 * q + 3]);
        }
    } else if (half == 0) {
        // P block: cols 0..31 = (h, pd); write 8 float4s
#pragma unroll
        for (int hh = 0; hh < 8; hh++) {
            float4 v = *(const float4*)&src[hh * 4];
            *(float4*)&g_P[(((size_t)(bb2 * NH + hh)) * SEQ + s) * PD] = v;
        }
    }
}

// ---------------------------------------------------------------------------
// Kernel 2: unchanged from round 9 (203us, passing).
// ---------------------------------------------------------------------------
#define KPITCH 144
#define SCK 256
#define SCP 1032

#define SC_OFF  0
#define K_OFF   66048
#define Q_OFF   (66048 + 36864)
#define PS_OFF  (Q_OFF + 2304)
#define SM_TOTAL (PS_OFF + 256)

__global__ __launch_bounds__(256, 2)
void attn_mma_kernel(const float* __restrict__ pos, const float* __restrict__ off,
                     float* __restrict__ out)
{
    extern __shared__ __align__(16) char smraw[];
    float* sc = (float*)(smraw + SC_OFF);
    char* Ksm = smraw + K_OFF;
    char* Qsm = smraw + Q_OFF;
    float4* Ps = (float4*)(smraw + PS_OFF);

    const int tid = threadIdx.x;
    const int w = tid >> 5, lane = tid & 31;
    const int t0g = blockIdx.x * 16;
    const int h = blockIdx.y, b = blockIdx.z;

    const char* Qg = g_Qhl + (((size_t)(b * NH + h)) * SEQ + t0g) * 128;
    const char* Kg = g_Khl + ((size_t)(b * NH + h)) * SEQ * 128;
    const float* Pg = g_P + ((size_t)(b * NH + h)) * SEQ * PD;

    if (tid < 128) {
        const int r = tid >> 3, oct = tid & 7;
        *(uint4*)(Qsm + r * KPITCH + oct * 16) =
            *(const uint4*)(Qg + (size_t)r * 128 + oct * 16);
    }
    if (tid < 16)
        Ps[tid] = *(const float4*)&Pg[(size_t)(t0g + tid) * PD];
    __syncthreads();

    const uint32_t Qaddr = smem_u32(Qsm);
    const uint32_t Kaddr = smem_u32(Ksm);

    uint32_t aq[2][2][4];
    {
        const int arow = (lane & 7) + ((lane >> 3) & 1) * 8;
        const int ab = ((lane >> 4) & 1) * 16;
#pragma unroll
        for (int prec = 0; prec < 2; prec++)
#pragma unroll
            for (int kk = 0; kk < 2; kk++) {
                const uint32_t ad = Qaddr + arow * KPITCH + ab + kk * 32 + prec * 64;
                LDSM4(aq[prec][kk][0], aq[prec][kk][1],
                      aq[prec][kk][2], aq[prec][kk][3], ad);
            }
    }

    const int r0 = lane >> 2, r1 = r0 + 8;
    const int scol = 2 * (lane & 3);

#pragma unroll
    for (int ch = 0; ch < 4; ch++) {
        __syncthreads();
#pragma unroll
        for (int i = 0; i < 8; i++) {
            const int idx = tid + i * 256;
            const int r = idx >> 3, oct = idx & 7;
            *(uint4*)(Ksm + r * KPITCH + oct * 16) =
                *(const uint4*)(Kg + (size_t)(ch * SCK + r) * 128 + oct * 16);
        }
        __syncthreads();

#pragma unroll
        for (int j = 0; j < 4; j++) {
            const int s0loc = w * 32 + j * 8;
            uint32_t bh[4], bl[4];
            {
                const uint32_t bad = Kaddr + (s0loc + (lane & 7)) * KPITCH +
                                     (lane >> 3) * 16;
                LDSM4(bh[0], bh[1], bh[2], bh[3], bad);
                LDSM4(bl[0], bl[1], bl[2], bl[3], bad + 64);
            }
            float ac[4] = {0.f, 0.f, 0.f, 0.f};
            mma16816(ac, aq[0][0], bh[0], bh[1]);
            mma16816(ac, aq[0][1], bh[2], bh[3]);
            mma16816(ac, aq[0][0], bl[0], bl[1]);
            mma16816(ac, aq[0][1], bl[2], bl[3]);
            mma16816(ac, aq[1][0], bh[0], bh[1]);
            mma16816(ac, aq[1][1], bh[2], bh[3]);

            const int col = ch * SCK + s0loc + scol;
            *(float2*)&sc[r0 * SCP + col] = make_float2(ac[0], ac[1]);
            *(float2*)&sc[r1 * SCP + col] = make_float2(ac[2], ac[3]);
        }
    }
    __syncthreads();

#pragma unroll
    for (int rr = 0; rr < 2; rr++) {
        const int tl = w * 2 + rr;
        const int t = t0g + tl;
        const float4 p4 = Ps[tl];
        const float* posrow = pos + (size_t)t * SEQ * PD;
        const float* offrow = off + ((size_t)b * SEQ + t) * SEQ;
        float* scrow = &sc[tl * SCP];

        float sum = 0.f;
#pragma unroll
        for (int i = 0; i < 32; i++) {
            const int s = i * 32 + lane;
            float v = scrow[s];
            const float4 pe = *(const float4*)&posrow[(size_t)s * PD];
            const float o = offrow[s];
            v += p4.x * pe.x + p4.y * pe.y + p4.z * pe.z + p4.w * pe.w + o;
            v = __expf(v);
            scrow[s] = v;
            sum += v;
        }
#pragma unroll
        for (int o_ = 16; o_ > 0; o_ >>= 1)
            sum += __shfl_xor_sync(0xffffffffu, sum, o_);
        const float inv = 1.0f / sum;

        float* orow = &out[(((size_t)(h * BSZ + b)) * SEQ + t) * SEQ];
#pragma unroll
        for (int i = 0; i < 8; i++) {
            float4 v = *(const float4*)&scrow[i * 128 + lane * 4];
            v.x *= inv; v.y *= inv; v.z *= inv; v.w *= inv;
            *(float4*)&orow[i * 128 + lane * 4] = v;
        }
    }
}

// ---------------------------------------------------------------------------
extern "C" void kernel_launch(void* const* d_in, const int* in_sizes, int n_in,
                              void* d_out, int out_size)
{
    const float* x    = (const float*)d_in[0];
    const float* pos  = (const float*)d_in[1];
    const float* off  = (const float*)d_in[2];
    const float* W    = (const float*)d_in[3];
    const float* bias = (const float*)d_in[4];
    float* out = (float*)d_out;

    cudaFuncSetAttribute(proj_mma_kernel,
                         cudaFuncAttributeMaxDynamicSharedMemorySize, PROJ_SMEM);
    cudaFuncSetAttribute(attn_mma_kernel,
                         cudaFuncAttributeMaxDynamicSharedMemorySize, SM_TOTAL);

    dim3 gproj(9, (SEQ * BSZ) / 128);                     // 9 x 64
    proj_mma_kernel<<<gproj, 256, PROJ_SMEM>>>(x, W, bias);

    dim3 gattn(SEQ / 16, NH, BSZ);                        // 64 x 8 x 8
    attn_mma_kernel<<<gattn, 256, SM_TOTAL>>>(pos, off, out);
}

// round 11
// speedup vs baseline: 1.6978x; 1.0886x over previous
#include <cuda_runtime.h>
#include <cuda_bf16.h>
#include <cuda_fp16.h>
#include <cstdint>

#define SEQ 1024
#define BSZ 8
#define EMBED 512
#define NH 8
#define QHD 32
#define PD 4
#define IN_PROJ 544

// Q/K stored as packed hi/lo bf16 rows: 128B per (s) row = [hi bf16 x32 | lo bf16 x32]
__device__ __align__(16) char g_Qhl[BSZ * NH * SEQ * 128];   // 8 MB
__device__ __align__(16) char g_Khl[BSZ * NH * SEQ * 128];   // 8 MB
__device__ float g_P[BSZ * NH * SEQ * PD];                   // 1 MB
__device__ __align__(16) __half g_pos16[SEQ * SEQ * PD];     // 8 MB

// ---------------------------------------------------------------------------
// Kernel 0: pos f32 -> fp16 (read once per timed run; tiny)
// ---------------------------------------------------------------------------
__global__ __launch_bounds__(256) void pos_cvt_kernel(const float* __restrict__ pos)
{
    const int idx = blockIdx.x * 256 + threadIdx.x;   // over SEQ*SEQ
    const float4 v = ((const float4*)pos)[idx];
    __half2 a = __floats2half2_rn(v.x, v.y);
    __half2 b = __floats2half2_rn(v.z, v.w);
    uint2 pk;
    pk.x = *(uint32_t*)&a;
    pk.y = *(uint32_t*)&b;
    ((uint2*)g_pos16)[idx] = pk;
}

// ========================= warp-MMA plumbing (sm_80+) =======================
__device__ __forceinline__ uint32_t smem_u32(const void* p) {
    uint32_t a;
    asm("{ .reg .u64 t; cvta.to.shared.u64 t, %1; cvt.u32.u64 %0, t; }"
        : "=r"(a) : "l"(p));
    return a;
}

#define LDSM4(d0, d1, d2, d3, a) \
    asm volatile("ldmatrix.sync.aligned.m8n8.x4.shared.b16 {%0,%1,%2,%3}, [%4];" \
                 : "=r"(d0), "=r"(d1), "=r"(d2), "=r"(d3) : "r"(a))

__device__ __forceinline__ void mma16816(float* d, const uint32_t* a,
                                         uint32_t b0, uint32_t b1) {
    asm volatile(
        "mma.sync.aligned.m16n8k16.row.col.f32.bf16.bf16.f32 "
        "{%0,%1,%2,%3}, {%4,%5,%6,%7}, {%8,%9}, {%0,%1,%2,%3};"
        : "+f"(d[0]), "+f"(d[1]), "+f"(d[2]), "+f"(d[3])
        : "r"(a[0]), "r"(a[1]), "r"(a[2]), "r"(a[3]), "r"(b0), "r"(b1));
}

// split 8 consecutive f32 into hi/lo bf16x2 quads written to two SMEM planes
__device__ __forceinline__ void cvt8s(const float* __restrict__ src,
                                      char* __restrict__ hirow,
                                      char* __restrict__ lorow, int c,
                                      bool valid) {
    float f[8];
    if (valid) {
        float4 v0 = *(const float4*)src;
        float4 v1 = *(const float4*)(src + 4);
        f[0] = v0.x; f[1] = v0.y; f[2] = v0.z; f[3] = v0.w;
        f[4] = v1.x; f[5] = v1.y; f[6] = v1.z; f[7] = v1.w;
    } else {
#pragma unroll
        for (int i = 0; i < 8; i++) f[i] = 0.f;
    }
    uint32_t hp[4], lp[4];
#pragma unroll
    for (int p = 0; p < 4; p++) {
        float a = f[2 * p], bq = f[2 * p + 1];
        __nv_bfloat16 ah = __float2bfloat16(a);
        __nv_bfloat16 bh = __float2bfloat16(bq);
        __nv_bfloat162 hh; hh.x = ah; hh.y = bh;
        __nv_bfloat162 ll;
        ll.x = __float2bfloat16(a - __bfloat162float(ah));
        ll.y = __float2bfloat16(bq - __bfloat162float(bh));
        hp[p] = *(uint32_t*)&hh;
        lp[p] = *(uint32_t*)&ll;
    }
    *(uint4*)(hirow + c * 16) = make_uint4(hp[0], hp[1], hp[2], hp[3]);
    *(uint4*)(lorow + c * 16) = make_uint4(lp[0], lp[1], lp[2], lp[3]);
}

// ---------------------------------------------------------------------------
// Kernel 1: projection on HMMA (unchanged from round 10, ~49us).
// ---------------------------------------------------------------------------
#define PPITCH 144
#define XHI_OFF 0
#define XLO_OFF 18432
#define WHI_OFF 36864
#define WLO_OFF 46080
#define PROJ_SMEM 55296
#define OTP 68

__global__ __launch_bounds__(256, 2) void proj_mma_kernel(
    const float* __restrict__ x, const float* __restrict__ W,
    const float* __restrict__ bias)
{
    extern __shared__ __align__(16) char sm[];
    char* Xhi = sm + XHI_OFF;
    char* Xlo = sm + XLO_OFF;
    char* Whi = sm + WHI_OFF;
    char* Wlo = sm + WLO_OFF;
    float* OT = (float*)sm;

    const int tid = threadIdx.x;
    const int w = tid >> 5, lane = tid & 31;
    const int n0 = blockIdx.x * 64;
    const int m0 = blockIdx.y * 128;
    const int wm = w & 3;
    const int wn = w >> 2;

    const uint32_t XhiA = smem_u32(Xhi), XloA = smem_u32(Xlo);
    const uint32_t WhiA = smem_u32(Whi), WloA = smem_u32(Wlo);

    const int r0 = lane >> 2;
    const int scol = 2 * (lane & 3);

    float acc[2][4][4];
#pragma unroll
    for (int mt = 0; mt < 2; mt++)
#pragma unroll
        for (int nt = 0; nt < 4; nt++) {
            const int c = n0 + wn * 32 + nt * 8 + scol;
            const float b0v = (c < IN_PROJ) ? bias[c] : 0.f;
            const float b1v = (c + 1 < IN_PROJ) ? bias[c + 1] : 0.f;
            acc[mt][nt][0] = b0v; acc[mt][nt][1] = b1v;
            acc[mt][nt][2] = b0v; acc[mt][nt][3] = b1v;
        }

    for (int k0 = 0; k0 < EMBED; k0 += 64) {
        __syncthreads();
#pragma unroll
        for (int i = 0; i < 4; i++) {
            const int idx = tid + i * 256;
            const int r = idx >> 3, oct = idx & 7;
            cvt8s(&x[(size_t)(m0 + r) * EMBED + k0 + oct * 8],
                  Xhi + r * PPITCH, Xlo + r * PPITCH, oct, true);
        }
#pragma unroll
        for (int i = 0; i < 2; i++) {
            const int idx = tid + i * 256;
            const int r = idx >> 3, oct = idx & 7;
            cvt8s(&W[(size_t)(n0 + r) * EMBED + k0 + oct * 8],
                  Whi + r * PPITCH, Wlo + r * PPITCH, oct, n0 + r < IN_PROJ);
        }
        __syncthreads();

        const int arow = (lane & 7) + ((lane >> 3) & 1) * 8;
        const int ab = ((lane >> 4) & 1) * 16;
        const int brow = lane & 7, bb = (lane >> 3) * 16;

#pragma unroll
        for (int kh = 0; kh < 2; kh++) {
            uint32_t A[2][2][2][4];
#pragma unroll
            for (int mt = 0; mt < 2; mt++)
#pragma unroll
                for (int kr = 0; kr < 2; kr++) {
                    const uint32_t off =
                        (wm * 32 + mt * 16 + arow) * PPITCH + ab +
                        kh * 64 + kr * 32;
                    LDSM4(A[mt][0][kr][0], A[mt][0][kr][1],
                          A[mt][0][kr][2], A[mt][0][kr][3], XhiA + off);
                    LDSM4(A[mt][1][kr][0], A[mt][1][kr][1],
                          A[mt][1][kr][2], A[mt][1][kr][3], XloA + off);
                }
            uint32_t B[4][2][4];
#pragma unroll
            for (int nt = 0; nt < 4; nt++) {
                const uint32_t off =
                    (wn * 32 + nt * 8 + brow) * PPITCH + bb + kh * 64;
                LDSM4(B[nt][0][0], B[nt][0][1], B[nt][0][2], B[nt][0][3],
                      WhiA + off);
                LDSM4(B[nt][1][0], B[nt][1][1], B[nt][1][2], B[nt][1][3],
                      WloA + off);
            }
#pragma unroll
            for (int kr = 0; kr < 2; kr++)
#pragma unroll
                for (int mt = 0; mt < 2; mt++)
#pragma unroll
                    for (int nt = 0; nt < 4; nt++) {
                        mma16816(acc[mt][nt], A[mt][0][kr],
                                 B[nt][0][kr * 2], B[nt][0][kr * 2 + 1]);
                        mma16816(acc[mt][nt], A[mt][0][kr],
                                 B[nt][1][kr * 2], B[nt][1][kr * 2 + 1]);
                        mma16816(acc[mt][nt], A[mt][1][kr],
                                 B[nt][0][kr * 2], B[nt][0][kr * 2 + 1]);
                    }
        }
    }
    __syncthreads();

#pragma unroll
    for (int mt = 0; mt < 2; mt++)
#pragma unroll
        for (int nt = 0; nt < 4; nt++) {
            const int mr0 = wm * 32 + mt * 16 + r0;
            const int c = wn * 32 + nt * 8 + scol;
            *(float2*)&OT[mr0 * OTP + c] =
                make_float2(acc[mt][nt][0], acc[mt][nt][1]);
            *(float2*)&OT[(mr0 + 8) * OTP + c] =
                make_float2(acc[mt][nt][2], acc[mt][nt][3]);
        }
    __syncthreads();

    const int mr = tid >> 1, half = tid & 1;
    const int m = m0 + mr;
    const int s = m >> 3, bb2 = m & 7;
    const int nb = blockIdx.x;
    const float* src = &OT[mr * OTP + half * 32];

    if (nb < 8) {
        const int qk = nb >> 2;
        const int hh = (nb & 3) * 2 + half;
        char* row = (qk ? g_Khl : g_Qhl) +
                    (((size_t)(bb2 * NH + hh)) * SEQ + s) * 128;
        uint32_t hp[16], lp[16];
#pragma unroll
        for (int p = 0; p < 16; p++) {
            const float a = src[2 * p], bq = src[2 * p + 1];
            __nv_bfloat16 ah = __float2bfloat16(a);
            __nv_bfloat16 bh = __float2bfloat16(bq);
            __nv_bfloat162 hh2; hh2.x = ah; hh2.y = bh;
            __nv_bfloat162 ll;
            ll.x = __float2bfloat16(a - __bfloat162float(ah));
            ll.y = __float2bfloat16(bq - __bfloat162float(bh));
            hp[p] = *(uint32_t*)&hh2;
            lp[p] = *(uint32_t*)&ll;
        }
#pragma unroll
        for (int q = 0; q < 4; q++) {
            *(uint4*)(row + q * 16) =
                make_uint4(hp[4 * q], hp[4 * q + 1], hp[4 * q + 2], hp[4 * q + 3]);
            *(uint4*)(row + 64 + q * 16) =
                make_uint4(lp[4 * q], lp[4 * q + 1], lp[4 * q + 2], lp[4 * q + 3]);
        }
    } else if (half == 0) {
#pragma unroll
        for (int hh = 0; hh < 8; hh++) {
            float4 v = *(const float4*)&src[hh * 4];
            *(float4*)&g_P[(((size_t)(bb2 * NH + hh)) * SEQ + s) * PD] = v;
        }
    }
}

// ---------------------------------------------------------------------------
// Kernel 2: HMMA QK -> SMEM score tile; single-pass coalesced epilogue with
// fp16 pos and register-resident exp values.
// ---------------------------------------------------------------------------
#define KPITCH 144
#define SCK 256
#define SCP 1032

#define SC_OFF  0
#define K_OFF   66048
#define Q_OFF   (66048 + 36864)
#define PS_OFF  (Q_OFF + 2304)
#define SM_TOTAL (PS_OFF + 256)

__global__ __launch_bounds__(256, 2)
void attn_mma_kernel(const float* __restrict__ off, float* __restrict__ out)
{
    extern __shared__ __align__(16) char smraw[];
    float* sc = (float*)(smraw + SC_OFF);
    char* Ksm = smraw + K_OFF;
    char* Qsm = smraw + Q_OFF;
    float4* Ps = (float4*)(smraw + PS_OFF);

    const int tid = threadIdx.x;
    const int w = tid >> 5, lane = tid & 31;
    const int t0g = blockIdx.x * 16;
    const int h = blockIdx.y, b = blockIdx.z;

    const char* Qg = g_Qhl + (((size_t)(b * NH + h)) * SEQ + t0g) * 128;
    const char* Kg = g_Khl + ((size_t)(b * NH + h)) * SEQ * 128;
    const float* Pg = g_P + ((size_t)(b * NH + h)) * SEQ * PD;

    if (tid < 128) {
        const int r = tid >> 3, oct = tid & 7;
        *(uint4*)(Qsm + r * KPITCH + oct * 16) =
            *(const uint4*)(Qg + (size_t)r * 128 + oct * 16);
    }
    if (tid < 16)
        Ps[tid] = *(const float4*)&Pg[(size_t)(t0g + tid) * PD];
    __syncthreads();

    const uint32_t Qaddr = smem_u32(Qsm);
    const uint32_t Kaddr = smem_u32(Ksm);

    uint32_t aq[2][2][4];
    {
        const int arow = (lane & 7) + ((lane >> 3) & 1) * 8;
        const int ab = ((lane >> 4) & 1) * 16;
#pragma unroll
        for (int prec = 0; prec < 2; prec++)
#pragma unroll
            for (int kk = 0; kk < 2; kk++) {
                const uint32_t ad = Qaddr + arow * KPITCH + ab + kk * 32 + prec * 64;
                LDSM4(aq[prec][kk][0], aq[prec][kk][1],
                      aq[prec][kk][2], aq[prec][kk][3], ad);
            }
    }

    const int r0 = lane >> 2, r1 = r0 + 8;
    const int scol = 2 * (lane & 3);

    // ---- phase 1: MMA -> raw scores in SMEM tile ---------------------------
#pragma unroll
    for (int ch = 0; ch < 4; ch++) {
        __syncthreads();
#pragma unroll
        for (int i = 0; i < 8; i++) {
            const int idx = tid + i * 256;
            const int r = idx >> 3, oct = idx & 7;
            *(uint4*)(Ksm + r * KPITCH + oct * 16) =
                *(const uint4*)(Kg + (size_t)(ch * SCK + r) * 128 + oct * 16);
        }
        __syncthreads();

#pragma unroll
        for (int j = 0; j < 4; j++) {
            const int s0loc = w * 32 + j * 8;
            uint32_t bh[4], bl[4];
            {
                const uint32_t bad = Kaddr + (s0loc + (lane & 7)) * KPITCH +
                                     (lane >> 3) * 16;
                LDSM4(bh[0], bh[1], bh[2], bh[3], bad);
                LDSM4(bl[0], bl[1], bl[2], bl[3], bad + 64);
            }
            float ac[4] = {0.f, 0.f, 0.f, 0.f};
            mma16816(ac, aq[0][0], bh[0], bh[1]);
            mma16816(ac, aq[0][1], bh[2], bh[3]);
            mma16816(ac, aq[0][0], bl[0], bl[1]);
            mma16816(ac, aq[0][1], bl[2], bl[3]);
            mma16816(ac, aq[1][0], bh[0], bh[1]);
            mma16816(ac, aq[1][1], bh[2], bh[3]);

            const int col = ch * SCK + s0loc + scol;
            *(float2*)&sc[r0 * SCP + col] = make_float2(ac[0], ac[1]);
            *(float2*)&sc[r1 * SCP + col] = make_float2(ac[2], ac[3]);
        }
    }
    __syncthreads();

    // ---- phase 2: single-pass epilogue (warp = t-row, exp in registers) ----
#pragma unroll
    for (int rr = 0; rr < 2; rr++) {
        const int tl = w * 2 + rr;
        const int t = t0g + tl;
        const float4 p4 = Ps[tl];
        const uint2* posrow = (const uint2*)(g_pos16 + (size_t)t * SEQ * PD);
        const float* offrow = off + ((size_t)b * SEQ + t) * SEQ;
        const float* scrow = &sc[tl * SCP];

        float v[32];
        float sum = 0.f;
#pragma unroll
        for (int i = 0; i < 32; i++) {
            const int s = i * 32 + lane;
            const uint2 pp = posrow[s];                 // 8B fp16 pos[4]
            const __half2 h0 = *(const __half2*)&pp.x;
            const __half2 h1 = *(const __half2*)&pp.y;
            const float2 f0 = __half22float2(h0);
            const float2 f1 = __half22float2(h1);
            float val = scrow[s] + offrow[s] +
                        p4.x * f0.x + p4.y * f0.y + p4.z * f1.x + p4.w * f1.y;
            val = __expf(val);
            v[i] = val;
            sum += val;
        }
#pragma unroll
        for (int o_ = 16; o_ > 0; o_ >>= 1)
            sum += __shfl_xor_sync(0xffffffffu, sum, o_);
        const float inv = 1.0f / sum;

        float* orow = &out[(((size_t)(h * BSZ + b)) * SEQ + t) * SEQ];
#pragma unroll
        for (int i = 0; i < 32; i++)
            orow[i * 32 + lane] = v[i] * inv;
    }
}

// ---------------------------------------------------------------------------
extern "C" void kernel_launch(void* const* d_in, const int* in_sizes, int n_in,
                              void* d_out, int out_size)
{
    const float* x    = (const float*)d_in[0];
    const float* pos  = (const float*)d_in[1];
    const float* off  = (const float*)d_in[2];
    const float* W    = (const float*)d_in[3];
    const float* bias = (const float*)d_in[4];
    float* out = (float*)d_out;

    cudaFuncSetAttribute(proj_mma_kernel,
                         cudaFuncAttributeMaxDynamicSharedMemorySize, PROJ_SMEM);
    cudaFuncSetAttribute(attn_mma_kernel,
                         cudaFuncAttributeMaxDynamicSharedMemorySize, SM_TOTAL);

    pos_cvt_kernel<<<(SEQ * SEQ) / 256, 256>>>(pos);

    dim3 gproj(9, (SEQ * BSZ) / 128);                     // 9 x 64
    proj_mma_kernel<<<gproj, 256, PROJ_SMEM>>>(x, W, bias);

    dim3 gattn(SEQ / 16, NH, BSZ);                        // 64 x 8 x 8
    attn_mma_kernel<<<gattn, 256, SM_TOTAL>>>(off, out);
}

// round 12
// speedup vs baseline: 1.7158x; 1.0106x over previous
#include <cuda_runtime.h>
#include <cuda_bf16.h>
#include <cuda_fp16.h>
#include <cstdint>

#define SEQ 1024
#define BSZ 8
#define EMBED 512
#define NH 8
#define QHD 32
#define PD 4
#define IN_PROJ 544

// Q/K stored as packed hi/lo bf16 rows: 128B per (s) row = [hi bf16 x32 | lo bf16 x32]
__device__ __align__(16) char g_Qhl[BSZ * NH * SEQ * 128];   // 8 MB
__device__ __align__(16) char g_Khl[BSZ * NH * SEQ * 128];   // 8 MB
__device__ float g_P[BSZ * NH * SEQ * PD];                   // 1 MB
__device__ __align__(16) __half g_pos16[SEQ * SEQ * PD];     // 8 MB

// ---------------------------------------------------------------------------
// Kernel 0: pos f32 -> fp16
// ---------------------------------------------------------------------------
__global__ __launch_bounds__(256) void pos_cvt_kernel(const float* __restrict__ pos)
{
    const int idx = blockIdx.x * 256 + threadIdx.x;   // over SEQ*SEQ
    const float4 v = ((const float4*)pos)[idx];
    __half2 a = __floats2half2_rn(v.x, v.y);
    __half2 b = __floats2half2_rn(v.z, v.w);
    uint2 pk;
    pk.x = *(uint32_t*)&a;
    pk.y = *(uint32_t*)&b;
    ((uint2*)g_pos16)[idx] = pk;
}

// ========================= warp-MMA plumbing (sm_80+) =======================
__device__ __forceinline__ uint32_t smem_u32(const void* p) {
    uint32_t a;
    asm("{ .reg .u64 t; cvta.to.shared.u64 t, %1; cvt.u32.u64 %0, t; }"
        : "=r"(a) : "l"(p));
    return a;
}

#define LDSM4(d0, d1, d2, d3, a) \
    asm volatile("ldmatrix.sync.aligned.m8n8.x4.shared.b16 {%0,%1,%2,%3}, [%4];" \
                 : "=r"(d0), "=r"(d1), "=r"(d2), "=r"(d3) : "r"(a))

__device__ __forceinline__ void mma16816(float* d, const uint32_t* a,
                                         uint32_t b0, uint32_t b1) {
    asm volatile(
        "mma.sync.aligned.m16n8k16.row.col.f32.bf16.bf16.f32 "
        "{%0,%1,%2,%3}, {%4,%5,%6,%7}, {%8,%9}, {%0,%1,%2,%3};"
        : "+f"(d[0]), "+f"(d[1]), "+f"(d[2]), "+f"(d[3])
        : "r"(a[0]), "r"(a[1]), "r"(a[2]), "r"(a[3]), "r"(b0), "r"(b1));
}

// split 8 consecutive f32 into hi/lo bf16x2 quads written to two SMEM planes
__device__ __forceinline__ void cvt8s(const float* __restrict__ src,
                                      char* __restrict__ hirow,
                                      char* __restrict__ lorow, int c,
                                      bool valid) {
    float f[8];
    if (valid) {
        float4 v0 = *(const float4*)src;
        float4 v1 = *(const float4*)(src + 4);
        f[0] = v0.x; f[1] = v0.y; f[2] = v0.z; f[3] = v0.w;
        f[4] = v1.x; f[5] = v1.y; f[6] = v1.z; f[7] = v1.w;
    } else {
#pragma unroll
        for (int i = 0; i < 8; i++) f[i] = 0.f;
    }
    uint32_t hp[4], lp[4];
#pragma unroll
    for (int p = 0; p < 4; p++) {
        float a = f[2 * p], bq = f[2 * p + 1];
        __nv_bfloat16 ah = __float2bfloat16(a);
        __nv_bfloat16 bh = __float2bfloat16(bq);
        __nv_bfloat162 hh; hh.x = ah; hh.y = bh;
        __nv_bfloat162 ll;
        ll.x = __float2bfloat16(a - __bfloat162float(ah));
        ll.y = __float2bfloat16(bq - __bfloat162float(bh));
        hp[p] = *(uint32_t*)&hh;
        lp[p] = *(uint32_t*)&ll;
    }
    *(uint4*)(hirow + c * 16) = make_uint4(hp[0], hp[1], hp[2], hp[3]);
    *(uint4*)(lorow + c * 16) = make_uint4(lp[0], lp[1], lp[2], lp[3]);
}

// ---------------------------------------------------------------------------
// Kernel 1: projection on HMMA (unchanged, ~49us).
// ---------------------------------------------------------------------------
#define PPITCH 144
#define XHI_OFF 0
#define XLO_OFF 18432
#define WHI_OFF 36864
#define WLO_OFF 46080
#define PROJ_SMEM 55296
#define OTP 68

__global__ __launch_bounds__(256, 2) void proj_mma_kernel(
    const float* __restrict__ x, const float* __restrict__ W,
    const float* __restrict__ bias)
{
    extern __shared__ __align__(16) char sm[];
    char* Xhi = sm + XHI_OFF;
    char* Xlo = sm + XLO_OFF;
    char* Whi = sm + WHI_OFF;
    char* Wlo = sm + WLO_OFF;
    float* OT = (float*)sm;

    const int tid = threadIdx.x;
    const int w = tid >> 5, lane = tid & 31;
    const int n0 = blockIdx.x * 64;
    const int m0 = blockIdx.y * 128;
    const int wm = w & 3;
    const int wn = w >> 2;

    const uint32_t XhiA = smem_u32(Xhi), XloA = smem_u32(Xlo);
    const uint32_t WhiA = smem_u32(Whi), WloA = smem_u32(Wlo);

    const int r0 = lane >> 2;
    const int scol = 2 * (lane & 3);

    float acc[2][4][4];
#pragma unroll
    for (int mt = 0; mt < 2; mt++)
#pragma unroll
        for (int nt = 0; nt < 4; nt++) {
            const int c = n0 + wn * 32 + nt * 8 + scol;
            const float b0v = (c < IN_PROJ) ? bias[c] : 0.f;
            const float b1v = (c + 1 < IN_PROJ) ? bias[c + 1] : 0.f;
            acc[mt][nt][0] = b0v; acc[mt][nt][1] = b1v;
            acc[mt][nt][2] = b0v; acc[mt][nt][3] = b1v;
        }

    for (int k0 = 0; k0 < EMBED; k0 += 64) {
        __syncthreads();
#pragma unroll
        for (int i = 0; i < 4; i++) {
            const int idx = tid + i * 256;
            const int r = idx >> 3, oct = idx & 7;
            cvt8s(&x[(size_t)(m0 + r) * EMBED + k0 + oct * 8],
                  Xhi + r * PPITCH, Xlo + r * PPITCH, oct, true);
        }
#pragma unroll
        for (int i = 0; i < 2; i++) {
            const int idx = tid + i * 256;
            const int r = idx >> 3, oct = idx & 7;
            cvt8s(&W[(size_t)(n0 + r) * EMBED + k0 + oct * 8],
                  Whi + r * PPITCH, Wlo + r * PPITCH, oct, n0 + r < IN_PROJ);
        }
        __syncthreads();

        const int arow = (lane & 7) + ((lane >> 3) & 1) * 8;
        const int ab = ((lane >> 4) & 1) * 16;
        const int brow = lane & 7, bb = (lane >> 3) * 16;

#pragma unroll
        for (int kh = 0; kh < 2; kh++) {
            uint32_t A[2][2][2][4];
#pragma unroll
            for (int mt = 0; mt < 2; mt++)
#pragma unroll
                for (int kr = 0; kr < 2; kr++) {
                    const uint32_t off =
                        (wm * 32 + mt * 16 + arow) * PPITCH + ab +
                        kh * 64 + kr * 32;
                    LDSM4(A[mt][0][kr][0], A[mt][0][kr][1],
                          A[mt][0][kr][2], A[mt][0][kr][3], XhiA + off);
                    LDSM4(A[mt][1][kr][0], A[mt][1][kr][1],
                          A[mt][1][kr][2], A[mt][1][kr][3], XloA + off);
                }
            uint32_t B[4][2][4];
#pragma unroll
            for (int nt = 0; nt < 4; nt++) {
                const uint32_t off =
                    (wn * 32 + nt * 8 + brow) * PPITCH + bb + kh * 64;
                LDSM4(B[nt][0][0], B[nt][0][1], B[nt][0][2], B[nt][0][3],
                      WhiA + off);
                LDSM4(B[nt][1][0], B[nt][1][1], B[nt][1][2], B[nt][1][3],
                      WloA + off);
            }
#pragma unroll
            for (int kr = 0; kr < 2; kr++)
#pragma unroll
                for (int mt = 0; mt < 2; mt++)
#pragma unroll
                    for (int nt = 0; nt < 4; nt++) {
                        mma16816(acc[mt][nt], A[mt][0][kr],
                                 B[nt][0][kr * 2], B[nt][0][kr * 2 + 1]);
                        mma16816(acc[mt][nt], A[mt][0][kr],
                                 B[nt][1][kr * 2], B[nt][1][kr * 2 + 1]);
                        mma16816(acc[mt][nt], A[mt][1][kr],
                                 B[nt][0][kr * 2], B[nt][0][kr * 2 + 1]);
                    }
        }
    }
    __syncthreads();

#pragma unroll
    for (int mt = 0; mt < 2; mt++)
#pragma unroll
        for (int nt = 0; nt < 4; nt++) {
            const int mr0 = wm * 32 + mt * 16 + r0;
            const int c = wn * 32 + nt * 8 + scol;
            *(float2*)&OT[mr0 * OTP + c] =
                make_float2(acc[mt][nt][0], acc[mt][nt][1]);
            *(float2*)&OT[(mr0 + 8) * OTP + c] =
                make_float2(acc[mt][nt][2], acc[mt][nt][3]);
        }
    __syncthreads();

    const int mr = tid >> 1, half = tid & 1;
    const int m = m0 + mr;
    const int s = m >> 3, bb2 = m & 7;
    const int nb = blockIdx.x;
    const float* src = &OT[mr * OTP + half * 32];

    if (nb < 8) {
        const int qk = nb >> 2;
        const int hh = (nb & 3) * 2 + half;
        char* row = (qk ? g_Khl : g_Qhl) +
                    (((size_t)(bb2 * NH + hh)) * SEQ + s) * 128;
        uint32_t hp[16], lp[16];
#pragma unroll
        for (int p = 0; p < 16; p++) {
            const float a = src[2 * p], bq = src[2 * p + 1];
            __nv_bfloat16 ah = __float2bfloat16(a);
            __nv_bfloat16 bh = __float2bfloat16(bq);
            __nv_bfloat162 hh2; hh2.x = ah; hh2.y = bh;
            __nv_bfloat162 ll;
            ll.x = __float2bfloat16(a - __bfloat162float(ah));
            ll.y = __float2bfloat16(bq - __bfloat162float(bh));
            hp[p] = *(uint32_t*)&hh2;
            lp[p] = *(uint32_t*)&ll;
        }
#pragma unroll
        for (int q = 0; q < 4; q++) {
            *(uint4*)(row + q * 16) =
                make_uint4(hp[4 * q], hp[4 * q + 1], hp[4 * q + 2], hp[4 * q + 3]);
            *(uint4*)(row + 64 + q * 16) =
                make_uint4(lp[4 * q], lp[4 * q + 1], lp[4 * q + 2], lp[4 * q + 3]);
        }
    } else if (half == 0) {
#pragma unroll
        for (int hh = 0; hh < 8; hh++) {
            float4 v = *(const float4*)&src[hh * 4];
            *(float4*)&g_P[(((size_t)(bb2 * NH + hh)) * SEQ + s) * PD] = v;
        }
    }
}

// ---------------------------------------------------------------------------
// Kernel 2: HMMA QK, TT=32, 512 threads. Score tile 32x1024 in SMEM, SCK=512
// K chunks (2 stages). Phase 2: warp = t-row, fp16 pos, register exp.
// ---------------------------------------------------------------------------
#define KPITCH 144
#define SCK 512
#define SCP 1032

#define SC_OFF  0                           // 32*1032*4 = 132096
#define K_OFF   132096                      // 512*144 = 73728
#define Q_OFF   (132096 + 73728)            // 32*144 = 4608
#define PS_OFF  (Q_OFF + 4608)              // 32*16 = 512
#define SM_TOTAL (PS_OFF + 512)             // 210944 B

__global__ __launch_bounds__(512, 1)
void attn_mma_kernel(const float* __restrict__ off, float* __restrict__ out)
{
    extern __shared__ __align__(16) char smraw[];
    float* sc = (float*)(smraw + SC_OFF);
    char* Ksm = smraw + K_OFF;
    char* Qsm = smraw + Q_OFF;
    float4* Ps = (float4*)(smraw + PS_OFF);

    const int tid = threadIdx.x;
    const int w = tid >> 5, lane = tid & 31;
    const int t0g = blockIdx.x * 32;
    const int h = blockIdx.y, b = blockIdx.z;

    const char* Qg = g_Qhl + (((size_t)(b * NH + h)) * SEQ + t0g) * 128;
    const char* Kg = g_Khl + ((size_t)(b * NH + h)) * SEQ * 128;
    const float* Pg = g_P + ((size_t)(b * NH + h)) * SEQ * PD;

    // stage Q rows (32 x 128B) + P
    if (tid < 256) {
        const int r = tid >> 3, oct = tid & 7;
        *(uint4*)(Qsm + r * KPITCH + oct * 16) =
            *(const uint4*)(Qg + (size_t)r * 128 + oct * 16);
    }
    if (tid < 32)
        Ps[tid] = *(const float4*)&Pg[(size_t)(t0g + tid) * PD];
    __syncthreads();

    const uint32_t Qaddr = smem_u32(Qsm);
    const uint32_t Kaddr = smem_u32(Ksm);

    // A fragments: [mt][prec][kstep][4] for the two m16 tiles
    uint32_t aq[2][2][2][4];
    {
        const int arow = (lane & 7) + ((lane >> 3) & 1) * 8;
        const int ab = ((lane >> 4) & 1) * 16;
#pragma unroll
        for (int mt = 0; mt < 2; mt++)
#pragma unroll
            for (int prec = 0; prec < 2; prec++)
#pragma unroll
                for (int kk = 0; kk < 2; kk++) {
                    const uint32_t ad = Qaddr + (mt * 16 + arow) * KPITCH +
                                        ab + kk * 32 + prec * 64;
                    LDSM4(aq[mt][prec][kk][0], aq[mt][prec][kk][1],
                          aq[mt][prec][kk][2], aq[mt][prec][kk][3], ad);
                }
    }

    const int r0 = lane >> 2, r1 = r0 + 8;
    const int scol = 2 * (lane & 3);

    // ---- phase 1: MMA -> raw scores in SMEM tile ---------------------------
#pragma unroll
    for (int ch = 0; ch < 2; ch++) {
        __syncthreads();   // previous chunk's B-frags consumed
        // stage K chunk: 512 rows x 8 uint4 = 4096 slots over 512 threads
#pragma unroll
        for (int i = 0; i < 8; i++) {
            const int idx = tid + i * 512;
            const int r = idx >> 3, oct = idx & 7;
            *(uint4*)(Ksm + r * KPITCH + oct * 16) =
                *(const uint4*)(Kg + (size_t)(ch * SCK + r) * 128 + oct * 16);
        }
        __syncthreads();

#pragma unroll
        for (int j = 0; j < 4; j++) {
            const int s0loc = w * 32 + j * 8;   // 16 warps x 32 = 512 s
            uint32_t bh[4], bl[4];
            {
                const uint32_t bad = Kaddr + (s0loc + (lane & 7)) * KPITCH +
                                     (lane >> 3) * 16;
                LDSM4(bh[0], bh[1], bh[2], bh[3], bad);
                LDSM4(bl[0], bl[1], bl[2], bl[3], bad + 64);
            }
            const int col = ch * SCK + s0loc + scol;
#pragma unroll
            for (int mt = 0; mt < 2; mt++) {
                float ac[4] = {0.f, 0.f, 0.f, 0.f};
                mma16816(ac, aq[mt][0][0], bh[0], bh[1]);
                mma16816(ac, aq[mt][0][1], bh[2], bh[3]);
                mma16816(ac, aq[mt][0][0], bl[0], bl[1]);
                mma16816(ac, aq[mt][0][1], bl[2], bl[3]);
                mma16816(ac, aq[mt][1][0], bh[0], bh[1]);
                mma16816(ac, aq[mt][1][1], bh[2], bh[3]);

                *(float2*)&sc[(mt * 16 + r0) * SCP + col] =
                    make_float2(ac[0], ac[1]);
                *(float2*)&sc[(mt * 16 + r1) * SCP + col] =
                    make_float2(ac[2], ac[3]);
            }
        }
    }
    __syncthreads();

    // ---- phase 2: single-pass epilogue (warp = t-row, exp in registers) ----
#pragma unroll
    for (int rr = 0; rr < 2; rr++) {
        const int tl = w * 2 + rr;
        const int t = t0g + tl;
        const float4 p4 = Ps[tl];
        const uint2* posrow = (const uint2*)(g_pos16 + (size_t)t * SEQ * PD);
        const float* offrow = off + ((size_t)b * SEQ + t) * SEQ;
        const float* scrow = &sc[tl * SCP];

        float v[32];
        float sum = 0.f;
#pragma unroll
        for (int i = 0; i < 32; i++) {
            const int s = i * 32 + lane;
            const uint2 pp = posrow[s];                 // 8B fp16 pos[4]
            const __half2 h0 = *(const __half2*)&pp.x;
            const __half2 h1 = *(const __half2*)&pp.y;
            const float2 f0 = __half22float2(h0);
            const float2 f1 = __half22float2(h1);
            float val = scrow[s] + offrow[s] +
                        p4.x * f0.x + p4.y * f0.y + p4.z * f1.x + p4.w * f1.y;
            val = __expf(val);
            v[i] = val;
            sum += val;
        }
#pragma unroll
        for (int o_ = 16; o_ > 0; o_ >>= 1)
            sum += __shfl_xor_sync(0xffffffffu, sum, o_);
        const float inv = 1.0f / sum;

        float* orow = &out[(((size_t)(h * BSZ + b)) * SEQ + t) * SEQ];
#pragma unroll
        for (int i = 0; i < 32; i++)
            orow[i * 32 + lane] = v[i] * inv;
    }
}

// ---------------------------------------------------------------------------
extern "C" void kernel_launch(void* const* d_in, const int* in_sizes, int n_in,
                              void* d_out, int out_size)
{
    const float* x    = (const float*)d_in[0];
    const float* pos  = (const float*)d_in[1];
    const float* off  = (const float*)d_in[2];
    const float* W    = (const float*)d_in[3];
    const float* bias = (const float*)d_in[4];
    float* out = (float*)d_out;

    cudaFuncSetAttribute(proj_mma_kernel,
                         cudaFuncAttributeMaxDynamicSharedMemorySize, PROJ_SMEM);
    cudaFuncSetAttribute(attn_mma_kernel,
                         cudaFuncAttributeMaxDynamicSharedMemorySize, SM_TOTAL);

    pos_cvt_kernel<<<(SEQ * SEQ) / 256, 256>>>(pos);

    dim3 gproj(9, (SEQ * BSZ) / 128);                     // 9 x 64
    proj_mma_kernel<<<gproj, 256, PROJ_SMEM>>>(x, W, bias);

    dim3 gattn(SEQ / 32, NH, BSZ);                        // 32 x 8 x 8
    attn_mma_kernel<<<gattn, 512, SM_TOTAL>>>(off, out);
}